// round 10
// baseline (speedup 1.0000x reference)
#include <cuda_runtime.h>
#include <cuda_fp16.h>
#include <math.h>

#define FULL 0xffffffffu

// ---------------- f32x2 packed-FMA helpers ----------------
__device__ __forceinline__ unsigned long long pack2(float a, float b) {
    unsigned long long r;
    asm("mov.b64 %0, {%1, %2};" : "=l"(r) : "f"(a), "f"(b));
    return r;
}
__device__ __forceinline__ float2 u2f(unsigned long long v) {
    float2 r;
    asm("mov.b64 {%0, %1}, %2;" : "=f"(r.x), "=f"(r.y) : "l"(v));
    return r;
}
__device__ __forceinline__ void fma2(unsigned long long& d, unsigned long long a, unsigned long long b) {
    asm("fma.rn.f32x2 %0, %1, %2, %0;" : "+l"(d) : "l"(a), "l"(b));
}
__device__ __forceinline__ float tanh_fast(float x) {
    float e = __expf(2.f * x);
    return (e - 1.f) / (e + 1.f);
}

// ---------------- scratch ----------------
__device__ __align__(16) float  g_W512[512*128];
__device__ float                g_b512[512];
__device__ __align__(16) float  g_WcombT[512*128];
__device__ __align__(16) __half g_Wvh[114688];
__device__ __align__(16) int2   g_mdA[524288];
__device__ __align__(16) uint4  g_mdB[524288];
__device__ __align__(16) __half g_v0ph[262144*32];
__device__ __align__(16) __half g_val1[32768*256];
__device__ __align__(16) __half g_val2[4096*256];
__device__ __align__(16) __half g_val3[512*256];
__device__ __align__(16) float  g_accA[4096*256];
__device__ __align__(16) float  g_accB[4096*256];
__device__ __align__(16) float  g_outbuf[128*4096];

// ---------------- K0: fold W512, build WcombT, build fp16 value weights ----------------
__global__ void k0_fold(const float* __restrict__ Woff, const float* __restrict__ Wwt,
                        const float* __restrict__ Wq,
                        const float* __restrict__ boff, const float* __restrict__ bwt,
                        const float* __restrict__ Wout, const float* __restrict__ Wv0,
                        const float* __restrict__ Wv1, const float* __restrict__ Wv2,
                        const float* __restrict__ Wv3) {
    const int b = blockIdx.x;
    const int t = threadIdx.x;
    if (b < 512) {
        const int j = b;
        const float* A = (j < 384) ? (Woff + j*192) : (Wwt + (j-384)*192);
        float s = 0.f;
        for (int m = 0; m < 192; m++) s += A[m] * Wq[m*128 + t];
        g_W512[j*128 + t] = s;
        if (t == 0) g_b512[j] = (j < 384) ? boff[j] : bwt[j-384];
    } else if (b < 640) {
        const int c = b - 512;
#pragma unroll
        for (int kk = 0; kk < 4; kk++) {
            int k = t + kk*128;
            float s;
            if (k < 256) {
                int h = k >> 5, q = k & 31;
                s = 0.f;
                for (int j = 0; j < 24; j++)
                    s += Wout[c*192 + h*24 + j] * Wv0[(h*24 + j)*32 + q];
            } else {
                int k2 = k - 256;
                int h = k2 >> 5, j = k2 & 31;
                s = (j < 24) ? Wout[c*192 + h*24 + j] : 0.f;
            }
            g_WcombT[k*128 + c] = s;
        }
    } else {
        int i = (b - 640)*128 + t;
        for (int idx = i; idx < 114688; idx += 8192) {
            int row, k, C;
            const float* W;
            if (idx < 16384)      { row = idx >> 6;  k = idx & 63;  C = 64;  W = Wv1; }
            else if (idx < 49152) { int d = idx - 16384; row = d >> 7; k = d & 127; C = 128; W = Wv2; }
            else                  { int d = idx - 49152; row = d >> 8; k = d & 255; C = 256; W = Wv3; }
            int h = row >> 5, j = row & 31;
            float v = (j < 24) ? W[(h*24 + j)*C + k] : 0.f;
            g_Wvh[idx] = __float2half_rn(v);
        }
    }
}

// ---------------- K1: 512x128 GEMM (f32x2, 512 threads) + fast epilogue + md emit ----------------
// grid 256 (N-tile 16), 512 threads: rg=tid>>2 (4 rows), cg=tid&3 (4 voxels)
#define K1PX 20
#define K1PW 516
__global__ void __launch_bounds__(512) k1_offaw(const float* __restrict__ qf) {
    __shared__ __align__(16) char sm1[43264];
    float* xs   = (float*)sm1;            // [128][20] = 10240B
    float* sW   = (float*)(sm1 + 10240);  // [16][516] = 33024B
    float* sbuf = (float*)sm1;            // reuse: [512][20] = 40960B

    const int nb = blockIdx.x * 16;
    const int tid = threadIdx.x;
    const int rg = tid >> 2, cg = tid & 3;
    const int rbase = rg * 4, vbase = cg * 4;

    for (int e = tid; e < 128*16; e += 512) {
        int k = e >> 4, v = e & 15;
        xs[k*K1PX + v] = qf[k*4096 + nb + v];
    }
    unsigned long long acc2[4][2];
#pragma unroll
    for (int i = 0; i < 4; i++) {
        float bv = g_b512[rbase + i];
        acc2[i][0] = pack2(bv, bv);
        acc2[i][1] = acc2[i][0];
    }

    for (int kc = 0; kc < 128; kc += 16) {
        __syncthreads();
        for (int e = tid; e < 512*4; e += 512) {
            int r = e >> 2, k4 = e & 3;
            float4 w4 = *(const float4*)&g_W512[r*128 + kc + k4*4];
            sW[(k4*4+0)*K1PW + r] = w4.x;
            sW[(k4*4+1)*K1PW + r] = w4.y;
            sW[(k4*4+2)*K1PW + r] = w4.z;
            sW[(k4*4+3)*K1PW + r] = w4.w;
        }
        __syncthreads();
#pragma unroll
        for (int k = 0; k < 16; k++) {
            float4 wa = *(const float4*)&sW[k*K1PW + rbase];
            float w[4] = {wa.x, wa.y, wa.z, wa.w};
            ulonglong2 xv = *(const ulonglong2*)&xs[(kc + k)*K1PX + vbase];
#pragma unroll
            for (int i = 0; i < 4; i++) {
                unsigned long long wp = pack2(w[i], w[i]);
                fma2(acc2[i][0], wp, xv.x);
                fma2(acc2[i][1], wp, xv.y);
            }
        }
    }
    __syncthreads();
#pragma unroll
    for (int i = 0; i < 4; i++) {
        float2 lo = u2f(acc2[i][0]), hi = u2f(acc2[i][1]);
        *(float4*)&sbuf[(rbase + i)*K1PX + vbase] = make_float4(lo.x, lo.y, hi.x, hi.y);
    }
    __syncthreads();

    // epilogue: unit = (h,v) handled by 4 threads (one scale each)
    {
        const int u = tid >> 2;           // 128 units: h*16+v
        const int h = u >> 4, v = u & 15;
        const int s = tid & 3;
        const int n = nb + v;
        const int wq = n & 15, hq = (n >> 4) & 15, dq = n >> 8;
        const float bgx = -1.f + (float)wq * (2.f/15.f);
        const float bgy = -1.f + (float)hq * (2.f/15.f);
        const float bgz = -1.f + (float)dq * (2.f/15.f);
        float e[16];
        float m = -1e30f;
#pragma unroll
        for (int j = 0; j < 16; j++) {
            e[j] = sbuf[(384 + h*16 + j)*K1PX + v];
            m = fmaxf(m, e[j]);
        }
        float sum = 0.f;
#pragma unroll
        for (int j = 0; j < 16; j++) { e[j] = __expf(e[j] - m); sum += e[j]; }
        const float inv = 1.f / sum;

        const int S = 64 >> s;
        const float fS = (float)S;
        const int stride = (s == 0) ? 32 : 256;
        const int hofs = (s == 0) ? 0 : h*32;
#pragma unroll
        for (int p = 0; p < 4; p++) {
            const int rb = ((h*4 + s)*4 + p) * 3;
            float gx = bgx + tanh_fast(sbuf[(rb+0)*K1PX + v]) * 0.35f;
            float gy = bgy + tanh_fast(sbuf[(rb+1)*K1PX + v]) * 0.35f;
            float gz = bgz + tanh_fast(sbuf[(rb+2)*K1PX + v]) * 0.35f;
            float ix = fminf(fmaxf(((gx + 1.f)*fS - 1.f)*0.5f, 0.f), fS - 1.f);
            float iy = fminf(fmaxf(((gy + 1.f)*fS - 1.f)*0.5f, 0.f), fS - 1.f);
            float iz = fminf(fmaxf(((gz + 1.f)*fS - 1.f)*0.5f, 0.f), fS - 1.f);
            float x0f = floorf(ix), y0f = floorf(iy), z0f = floorf(iz);
            float wx = ix - x0f, wy = iy - y0f, wz = iz - z0f;
            int x0 = (int)x0f, y0 = (int)y0f, z0 = (int)z0f;
            int flags = ((x0 < S-1) ? 4 : 0) | ((y0 < S-1) ? 2 : 0) | ((z0 < S-1) ? 1 : 0);
            int base = ((z0*S + y0)*S + x0)*stride + hofs;   // multiple of 32
            float aw = e[s*4 + p] * inv;
            float wx1 = 1.f - wx, wy1 = 1.f - wy, wz1 = 1.f - wz;
            float p00 = wz1*wy1, p01 = wz1*wy, p10 = wz*wy1, p11 = wz*wy;
            unsigned u0 = (unsigned)(p00*wx1*65535.f + 0.5f);
            unsigned u1 = (unsigned)(p00*wx *65535.f + 0.5f);
            unsigned u2 = (unsigned)(p01*wx1*65535.f + 0.5f);
            unsigned u3 = (unsigned)(p01*wx *65535.f + 0.5f);
            unsigned u4 = (unsigned)(p10*wx1*65535.f + 0.5f);
            unsigned u5 = (unsigned)(p10*wx *65535.f + 0.5f);
            unsigned u6 = (unsigned)(p11*wx1*65535.f + 0.5f);
            unsigned u7 = (unsigned)(p11*wx *65535.f + 0.5f);
            uint4 B = make_uint4((u1<<16)|u0, (u3<<16)|u2, (u5<<16)|u4, (u7<<16)|u6);
            int2 A = make_int2(base | flags, __float_as_int(aw * (1.f/65535.f)));
            int idx = (h*16 + s*4 + p)*4096 + n;
            g_mdA[idx] = A;
            g_mdB[idx] = B;
        }
    }
}

// ---------------- K23: merged k3 HMMA (blocks 0..583) + k2 transpose (584..2631) ----------------
__global__ void __launch_bounds__(256) k23_pack(const float* __restrict__ v0,
                                                const float* __restrict__ v1,
                                                const float* __restrict__ v2,
                                                const float* __restrict__ v3) {
    __shared__ __align__(16) char sm[34048];
    const int tid = threadIdx.x;
    const int b = blockIdx.x;

    if (b >= 584) {
        // ---- k2: transpose v0 -> fp16 [voxel][32] ----
        float* t = (float*)sm;   // [32][129]
        const int vb = (b - 584) * 128;
        for (int e = tid; e < 32*128; e += 256) {
            int c = e >> 7, v = e & 127;
            t[c*129 + v] = v0[c*262144 + vb + v];
        }
        __syncthreads();
        for (int e = tid; e < 512; e += 256) {
            int v = e >> 2, q = e & 3;
            union { uint4 u; __half2 h[4]; } o;
#pragma unroll
            for (int j = 0; j < 4; j++)
                o.h[j] = __floats2half2_rn(t[(q*8 + 2*j)*129 + v], t[(q*8 + 2*j + 1)*129 + v]);
            *reinterpret_cast<uint4*>(&g_v0ph[(vb + v)*32 + q*8]) = o.u;
        }
        return;
    }

    // ---- k3: HMMA projections scales 1..3 ----
    const float* vsrc; const __half* Wg; __half* outv;
    int C, Nv, nb;
    if (b < 512)      { vsrc = v1; Wg = g_Wvh;         outv = g_val1; C = 64;  Nv = 32768; nb = b*64; }
    else if (b < 576) { vsrc = v2; Wg = g_Wvh + 16384; outv = g_val2; C = 128; Nv = 4096;  nb = (b-512)*64; }
    else              { vsrc = v3; Wg = g_Wvh + 49152; outv = g_val3; C = 256; Nv = 512;   nb = (b-576)*64; }

    __half* Xt = (__half*)sm;     // [64][18]
    __half* Ds = (__half*)sm;     // reuse: [64][264]

    const int warp = tid >> 5, lane = tid & 31;
    const int grp = lane >> 2, tg = lane & 3;
    const int wbase = warp * 32;

    float acc[2][8][4];
#pragma unroll
    for (int mt = 0; mt < 2; mt++)
#pragma unroll
        for (int nt = 0; nt < 8; nt++)
#pragma unroll
            for (int i = 0; i < 4; i++) acc[mt][nt][i] = 0.f;

    const int xk = tid >> 4, xv = (tid & 15) * 4;

    for (int kc = 0; kc < C; kc += 16) {
        float4 x4 = *(const float4*)&vsrc[(size_t)(kc + xk)*Nv + nb + xv];
        Xt[(xv+0)*18 + xk] = __float2half_rn(x4.x);
        Xt[(xv+1)*18 + xk] = __float2half_rn(x4.y);
        Xt[(xv+2)*18 + xk] = __float2half_rn(x4.z);
        Xt[(xv+3)*18 + xk] = __float2half_rn(x4.w);
        __syncthreads();

        unsigned af[2][4];
#pragma unroll
        for (int mt = 0; mt < 2; mt++) {
            const __half* Ar = Wg + (size_t)(wbase + mt*16 + grp)*C + kc;
            af[mt][0] = *(const unsigned*)(Ar + 2*tg);
            af[mt][1] = *(const unsigned*)(Ar + 8*C + 2*tg);
            af[mt][2] = *(const unsigned*)(Ar + 2*tg + 8);
            af[mt][3] = *(const unsigned*)(Ar + 8*C + 2*tg + 8);
        }
#pragma unroll
        for (int nt = 0; nt < 8; nt++) {
            const __half* Br = Xt + (nt*8 + grp)*18 + 2*tg;
            unsigned b0 = *(const unsigned*)Br;
            unsigned b1 = *(const unsigned*)(Br + 8);
#pragma unroll
            for (int mt = 0; mt < 2; mt++) {
                asm volatile(
                    "mma.sync.aligned.m16n8k16.row.col.f32.f16.f16.f32 "
                    "{%0,%1,%2,%3}, {%4,%5,%6,%7}, {%8,%9}, {%0,%1,%2,%3};"
                    : "+f"(acc[mt][nt][0]), "+f"(acc[mt][nt][1]),
                      "+f"(acc[mt][nt][2]), "+f"(acc[mt][nt][3])
                    : "r"(af[mt][0]), "r"(af[mt][1]), "r"(af[mt][2]), "r"(af[mt][3]),
                      "r"(b0), "r"(b1));
            }
        }
        __syncthreads();
    }

#pragma unroll
    for (int mt = 0; mt < 2; mt++) {
        const int slot = wbase + mt*16 + grp;
#pragma unroll
        for (int nt = 0; nt < 8; nt++) {
            const int vv = nt*8 + 2*tg;
            Ds[vv*264 + slot]         = __float2half_rn(acc[mt][nt][0]);
            Ds[(vv+1)*264 + slot]     = __float2half_rn(acc[mt][nt][1]);
            Ds[vv*264 + slot + 8]     = __float2half_rn(acc[mt][nt][2]);
            Ds[(vv+1)*264 + slot + 8] = __float2half_rn(acc[mt][nt][3]);
        }
    }
    __syncthreads();
    for (int i = tid; i < 2048; i += 256) {
        int v = i >> 5, j = i & 31;
        *reinterpret_cast<uint4*>(&outv[(size_t)(nb + v)*256 + j*8]) =
            *reinterpret_cast<const uint4*>(&Ds[v*264 + j*8]);
    }
}

// ---------------- K4: gather with compact md ----------------
__global__ void __launch_bounds__(512) k4_sample() {
    const int tid = threadIdx.x;
    const int warp = tid >> 5, lane = tid & 31;
    const int gw = blockIdx.x*16 + warp;
    const int h = gw >> 12, n = gw & 4095;
    const int corner = lane >> 2, q8 = (lane & 3) * 8;
    const int cx = corner & 1, cy = (corner >> 1) & 1, cz = corner >> 2;
    const int sh = (corner & 1) * 16;

    float2 acc0[4], acc1[4];
#pragma unroll
    for (int j = 0; j < 4; j++) { acc0[j] = make_float2(0.f,0.f); acc1[j] = make_float2(0.f,0.f); }

    const int ptb = h*16*4096 + n;

    // scale 0: stride 32, S=64
    {
        const int dxc = cx ? 32 : 0, dyc = cy ? 64*32 : 0, dzc = cz ? 64*64*32 : 0;
#pragma unroll
        for (int p = 0; p < 4; p++) {
            int idx = ptb + p*4096;
            int2 A = g_mdA[idx];
            uint4 B = g_mdB[idx];
            int bf = A.x;
            int off = (bf & ~7) + q8 + ((bf & 4) ? dxc : 0) + ((bf & 2) ? dyc : 0) + ((bf & 1) ? dzc : 0);
            unsigned pw = (corner & 4) ? ((corner & 2) ? B.w : B.z) : ((corner & 2) ? B.y : B.x);
            float w = (float)((pw >> sh) & 0xffffu) * __int_as_float(A.y);
            union { uint4 u; __half2 hh[4]; } d;
            d.u = *reinterpret_cast<const uint4*>(g_v0ph + off);
#pragma unroll
            for (int j = 0; j < 4; j++) {
                float2 f = __half22float2(d.hh[j]);
                acc0[j].x += w*f.x; acc0[j].y += w*f.y;
            }
        }
    }
    // scales 1..3: stride 256
#pragma unroll
    for (int s = 1; s < 4; s++) {
        const __half* vptr = (s == 1) ? g_val1 : (s == 2) ? g_val2 : g_val3;
        const int S = 64 >> s;
        const int dxc = cx ? 256 : 0, dyc = cy ? S*256 : 0, dzc = cz ? S*S*256 : 0;
#pragma unroll
        for (int p = 0; p < 4; p++) {
            int idx = ptb + (s*4 + p)*4096;
            int2 A = g_mdA[idx];
            uint4 B = g_mdB[idx];
            int bf = A.x;
            int off = (bf & ~7) + q8 + ((bf & 4) ? dxc : 0) + ((bf & 2) ? dyc : 0) + ((bf & 1) ? dzc : 0);
            unsigned pw = (corner & 4) ? ((corner & 2) ? B.w : B.z) : ((corner & 2) ? B.y : B.x);
            float w = (float)((pw >> sh) & 0xffffu) * __int_as_float(A.y);
            union { uint4 u; __half2 hh[4]; } d;
            d.u = *reinterpret_cast<const uint4*>(vptr + off);
#pragma unroll
            for (int j = 0; j < 4; j++) {
                float2 f = __half22float2(d.hh[j]);
                acc1[j].x += w*f.x; acc1[j].y += w*f.y;
            }
        }
    }
#pragma unroll
    for (int m = 4; m <= 16; m <<= 1) {
#pragma unroll
        for (int j = 0; j < 4; j++) {
            acc0[j].x += __shfl_xor_sync(FULL, acc0[j].x, m);
            acc0[j].y += __shfl_xor_sync(FULL, acc0[j].y, m);
            acc1[j].x += __shfl_xor_sync(FULL, acc1[j].x, m);
            acc1[j].y += __shfl_xor_sync(FULL, acc1[j].y, m);
        }
    }
    if (lane < 4) {
        const int base = n*256 + h*32 + q8;
        *(float4*)&g_accA[base]     = make_float4(acc0[0].x, acc0[0].y, acc0[1].x, acc0[1].y);
        *(float4*)&g_accA[base + 4] = make_float4(acc0[2].x, acc0[2].y, acc0[3].x, acc0[3].y);
        *(float4*)&g_accB[base]     = make_float4(acc1[0].x, acc1[0].y, acc1[1].x, acc1[1].y);
        *(float4*)&g_accB[base + 4] = make_float4(acc1[2].x, acc1[2].y, acc1[3].x, acc1[3].y);
    }
}

// ---------------- K5: combined output GEMM [128][512] @ [512][4096], N-tile 32, grid 128 ----------------
#define K5PX 36
#define K5PW 132
__global__ void __launch_bounds__(256) k5_out() {
    __shared__ __align__(16) float xs[32*K5PX];
    __shared__ __align__(16) float sW[32*K5PW];
    const int tid = threadIdx.x;
    const int nb = blockIdx.x * 32;
    const int rg = tid >> 4, cg = tid & 15;
    const int rbase = rg * 8;
    const int lv = tid >> 3, lk = (tid & 7) * 4;

    unsigned long long acc2[8];
#pragma unroll
    for (int i = 0; i < 8; i++) acc2[i] = 0ull;

    for (int kc = 0; kc < 512; kc += 32) {
        __syncthreads();
        {
            const float* srcbuf = (kc < 256) ? g_accA : g_accB;
            const int ko = kc & 255;
            float4 x4 = *(const float4*)&srcbuf[(nb + lv)*256 + ko + lk];
            xs[(lk+0)*K5PX + lv] = x4.x;
            xs[(lk+1)*K5PX + lv] = x4.y;
            xs[(lk+2)*K5PX + lv] = x4.z;
            xs[(lk+3)*K5PX + lv] = x4.w;
        }
        for (int e = tid; e < 32*32; e += 256) {
            int k = e >> 5, c4 = e & 31;
            *(float4*)&sW[k*K5PW + c4*4] = *(const float4*)&g_WcombT[(kc + k)*128 + c4*4];
        }
        __syncthreads();
#pragma unroll
        for (int k = 0; k < 32; k++) {
            const float* wr = &sW[k*K5PW + rbase];
            float4 wa = *(const float4*)(wr);
            float4 wb = *(const float4*)(wr + 4);
            float w[8] = {wa.x, wa.y, wa.z, wa.w, wb.x, wb.y, wb.z, wb.w};
            unsigned long long xv = *(const unsigned long long*)&xs[k*K5PX + cg*2];
#pragma unroll
            for (int i = 0; i < 8; i++) {
                unsigned long long wp = pack2(w[i], w[i]);
                fma2(acc2[i], wp, xv);
            }
        }
    }
#pragma unroll
    for (int i = 0; i < 8; i++) {
        float2 f = u2f(acc2[i]);
        *(float2*)&g_outbuf[(rbase + i)*4096 + nb + cg*2] = f;
    }
}

// ---------------- K6: InstanceNorm per channel ----------------
__global__ void __launch_bounds__(256) k6_norm(const float* __restrict__ gamma,
                                               const float* __restrict__ beta,
                                               float* __restrict__ out) {
    const int c = blockIdx.x, tid = threadIdx.x;
    const float* row = &g_outbuf[c*4096];
    float s = 0.f, s2 = 0.f;
    for (int i = tid; i < 4096; i += 256) { float x = row[i]; s += x; s2 += x*x; }
#pragma unroll
    for (int m = 16; m > 0; m >>= 1) {
        s  += __shfl_xor_sync(FULL, s,  m);
        s2 += __shfl_xor_sync(FULL, s2, m);
    }
    __shared__ float rs[8], rq[8];
    __shared__ float smu, srstd;
    if ((tid & 31) == 0) { rs[tid >> 5] = s; rq[tid >> 5] = s2; }
    __syncthreads();
    if (tid == 0) {
        float ts = 0.f, tq = 0.f;
        for (int i = 0; i < 8; i++) { ts += rs[i]; tq += rq[i]; }
        float mu = ts * (1.f/4096.f);
        smu = mu;
        srstd = rsqrtf(tq * (1.f/4096.f) - mu*mu + 1e-5f);
    }
    __syncthreads();
    const float g = gamma[c] * srstd, b = beta[c], mu = smu;
    for (int i = tid; i < 4096; i += 256)
        out[c*4096 + i] = (row[i] - mu) * g + b;
}

// ---------------- launch ----------------
extern "C" void kernel_launch(void* const* d_in, const int* in_sizes, int n_in,
                              void* d_out, int out_size) {
    const float* qf    = (const float*)d_in[0];
    const float* v0    = (const float*)d_in[1];
    const float* v1    = (const float*)d_in[2];
    const float* v2    = (const float*)d_in[3];
    const float* v3    = (const float*)d_in[4];
    const float* Wq    = (const float*)d_in[5];
    const float* Wv0   = (const float*)d_in[6];
    const float* Wv1   = (const float*)d_in[7];
    const float* Wv2   = (const float*)d_in[8];
    const float* Wv3   = (const float*)d_in[9];
    const float* Woff  = (const float*)d_in[10];
    const float* boff  = (const float*)d_in[11];
    const float* Wwt   = (const float*)d_in[12];
    const float* bwt   = (const float*)d_in[13];
    const float* Wout  = (const float*)d_in[14];
    const float* gamma = (const float*)d_in[15];
    const float* beta  = (const float*)d_in[16];
    float* out = (float*)d_out;

    // Order chosen so ncu's captured launch (#4) is k4_sample this round.
    k0_fold<<<704, 128>>>(Woff, Wwt, Wq, boff, bwt, Wout, Wv0, Wv1, Wv2, Wv3);
    k1_offaw<<<256, 512>>>(qf);
    k23_pack<<<2632, 256>>>(v0, v1, v2, v3);
    k4_sample<<<2048, 512>>>();
    k5_out<<<128, 256>>>();
    k6_norm<<<128, 256>>>(gamma, beta, out);
}

// round 11
// speedup vs baseline: 1.2901x; 1.2901x over previous
#include <cuda_runtime.h>
#include <cuda_fp16.h>
#include <math.h>

#define FULL 0xffffffffu

// ---------------- f32x2 packed-FMA helpers ----------------
__device__ __forceinline__ unsigned long long pack2(float a, float b) {
    unsigned long long r;
    asm("mov.b64 %0, {%1, %2};" : "=l"(r) : "f"(a), "f"(b));
    return r;
}
__device__ __forceinline__ float2 u2f(unsigned long long v) {
    float2 r;
    asm("mov.b64 {%0, %1}, %2;" : "=f"(r.x), "=f"(r.y) : "l"(v));
    return r;
}
__device__ __forceinline__ void fma2(unsigned long long& d, unsigned long long a, unsigned long long b) {
    asm("fma.rn.f32x2 %0, %1, %2, %0;" : "+l"(d) : "l"(a), "l"(b));
}
__device__ __forceinline__ float tanh_fast(float x) {
    float e = __expf(2.f * x);
    return (e - 1.f) / (e + 1.f);
}

// ---------------- scratch ----------------
__device__ __align__(16) float  g_W512[512*128];
__device__ float                g_b512[512];
__device__ __align__(16) float  g_WcombT[512*128];
__device__ __align__(16) __half g_Wvh[114688];
__device__ __align__(16) int2   g_mdA[524288];     // per point: {base|flags, aw/65535}
__device__ __align__(16) uint4  g_mdB[524288];     // per point: 8x u16 corner products
__device__ __align__(16) __half g_v0ph[262144*32];
__device__ __align__(16) __half g_val1[32768*256];
__device__ __align__(16) __half g_val2[4096*256];
__device__ __align__(16) __half g_val3[512*256];
__device__ __align__(16) float  g_accA[4096*256];
__device__ __align__(16) float  g_accB[4096*256];
__device__ __align__(16) float  g_outbuf[128*4096];

// ---------------- K0: fold W512, build WcombT, build fp16 value weights ----------------
__global__ void k0_fold(const float* __restrict__ Woff, const float* __restrict__ Wwt,
                        const float* __restrict__ Wq,
                        const float* __restrict__ boff, const float* __restrict__ bwt,
                        const float* __restrict__ Wout, const float* __restrict__ Wv0,
                        const float* __restrict__ Wv1, const float* __restrict__ Wv2,
                        const float* __restrict__ Wv3) {
    const int b = blockIdx.x;
    const int t = threadIdx.x;
    if (b < 512) {
        const int j = b;
        const float* A = (j < 384) ? (Woff + j*192) : (Wwt + (j-384)*192);
        float s = 0.f;
        for (int m = 0; m < 192; m++) s += A[m] * Wq[m*128 + t];
        g_W512[j*128 + t] = s;
        if (t == 0) g_b512[j] = (j < 384) ? boff[j] : bwt[j-384];
    } else if (b < 640) {
        const int c = b - 512;
#pragma unroll
        for (int kk = 0; kk < 4; kk++) {
            int k = t + kk*128;
            float s;
            if (k < 256) {
                int h = k >> 5, q = k & 31;
                s = 0.f;
                for (int j = 0; j < 24; j++)
                    s += Wout[c*192 + h*24 + j] * Wv0[(h*24 + j)*32 + q];
            } else {
                int k2 = k - 256;
                int h = k2 >> 5, j = k2 & 31;
                s = (j < 24) ? Wout[c*192 + h*24 + j] : 0.f;
            }
            g_WcombT[k*128 + c] = s;
        }
    } else {
        int i = (b - 640)*128 + t;
        for (int idx = i; idx < 114688; idx += 8192) {
            int row, k, C;
            const float* W;
            if (idx < 16384)      { row = idx >> 6;  k = idx & 63;  C = 64;  W = Wv1; }
            else if (idx < 49152) { int d = idx - 16384; row = d >> 7; k = d & 127; C = 128; W = Wv2; }
            else                  { int d = idx - 49152; row = d >> 8; k = d & 255; C = 256; W = Wv3; }
            int h = row >> 5, j = row & 31;
            float v = (j < 24) ? W[(h*24 + j)*C + k] : 0.f;
            g_Wvh[idx] = __float2half_rn(v);
        }
    }
}

// ---------------- K2: transpose v0 -> fp16 [voxel][32] ----------------
__global__ void __launch_bounds__(256) k2_packv0(const float* __restrict__ v0) {
    __shared__ float t[32*129];
    const int vb = blockIdx.x * 128;
    const int tid = threadIdx.x;
    for (int e = tid; e < 32*128; e += 256) {
        int c = e >> 7, v = e & 127;
        t[c*129 + v] = v0[c*262144 + vb + v];
    }
    __syncthreads();
    for (int e = tid; e < 512; e += 256) {
        int v = e >> 2, q = e & 3;
        union { uint4 u; __half2 h[4]; } o;
#pragma unroll
        for (int j = 0; j < 4; j++)
            o.h[j] = __floats2half2_rn(t[(q*8 + 2*j)*129 + v], t[(q*8 + 2*j + 1)*129 + v]);
        *reinterpret_cast<uint4*>(&g_v0ph[(vb + v)*32 + q*8]) = o.u;
    }
}

// ---------------- K13: merged k1 (blocks 0..255) + k3 HMMA (blocks 256..839) ----------------
#define K1PX 20
#define K1PW 516
__global__ void __launch_bounds__(256) k13_fused(const float* __restrict__ qf,
                                                 const float* __restrict__ v1,
                                                 const float* __restrict__ v2,
                                                 const float* __restrict__ v3) {
    __shared__ __align__(16) char sm1[43264];
    const int tid = threadIdx.x;
    const int b = blockIdx.x;

    if (b < 256) {
        // ================= k1 role: 512x128 GEMM + epilogue (R7 shape) =================
        float* xs   = (float*)sm1;            // [128][20]
        float* sW   = (float*)(sm1 + 10240);  // [16][516]
        float* sbuf = (float*)sm1;            // reuse: [512][20]

        const int nb = b * 16;
        const int rg = tid >> 2, cg = tid & 3;
        const int rbase = rg * 8, vbase = cg * 4;

        for (int e = tid; e < 128*16; e += 256) {
            int k = e >> 4, v = e & 15;
            xs[k*K1PX + v] = qf[k*4096 + nb + v];
        }
        unsigned long long acc2[8][2];
#pragma unroll
        for (int i = 0; i < 8; i++) {
            float bv = g_b512[rbase + i];
            acc2[i][0] = pack2(bv, bv);
            acc2[i][1] = acc2[i][0];
        }

        for (int kc = 0; kc < 128; kc += 16) {
            __syncthreads();
            for (int e = tid; e < 512*4; e += 256) {
                int r = e >> 2, k4 = e & 3;
                float4 w4 = *(const float4*)&g_W512[r*128 + kc + k4*4];
                sW[(k4*4+0)*K1PW + r] = w4.x;
                sW[(k4*4+1)*K1PW + r] = w4.y;
                sW[(k4*4+2)*K1PW + r] = w4.z;
                sW[(k4*4+3)*K1PW + r] = w4.w;
            }
            __syncthreads();
#pragma unroll
            for (int k = 0; k < 16; k++) {
                const float* wr = &sW[k*K1PW + rbase];
                float4 wa = *(const float4*)(wr);
                float4 wb = *(const float4*)(wr + 4);
                float w[8] = {wa.x,wa.y,wa.z,wa.w, wb.x,wb.y,wb.z,wb.w};
                ulonglong2 xv = *(const ulonglong2*)&xs[(kc + k)*K1PX + vbase];
#pragma unroll
                for (int i = 0; i < 8; i++) {
                    unsigned long long wp = pack2(w[i], w[i]);
                    fma2(acc2[i][0], wp, xv.x);
                    fma2(acc2[i][1], wp, xv.y);
                }
            }
        }
        __syncthreads();
#pragma unroll
        for (int i = 0; i < 8; i++) {
            float2 lo = u2f(acc2[i][0]), hi = u2f(acc2[i][1]);
            *(float4*)&sbuf[(rbase + i)*K1PX + vbase] = make_float4(lo.x, lo.y, hi.x, hi.y);
        }
        __syncthreads();

        // epilogue: unit u = (h,v); each thread handles 2 scales (8 points)
        const int u = tid >> 1;
        const int h = u >> 4, v = u & 15;
        const int n = nb + v;
        const int wq = n & 15, hq = (n >> 4) & 15, dq = n >> 8;
        const float bgx = -1.f + (float)wq * (2.f/15.f);
        const float bgy = -1.f + (float)hq * (2.f/15.f);
        const float bgz = -1.f + (float)dq * (2.f/15.f);
        float e[16];
        float m = -1e30f;
#pragma unroll
        for (int j = 0; j < 16; j++) {
            e[j] = sbuf[(384 + h*16 + j)*K1PX + v];
            m = fmaxf(m, e[j]);
        }
        float sum = 0.f;
#pragma unroll
        for (int j = 0; j < 16; j++) { e[j] = __expf(e[j] - m); sum += e[j]; }
        const float inv = 1.f / sum;
        const int sb = (tid & 1) * 2;
#pragma unroll
        for (int si = 0; si < 2; si++) {
            const int s = sb + si;
            const int S = 64 >> s;
            const float fS = (float)S;
            const int stride = (s == 0) ? 32 : 256;
            const int hofs = (s == 0) ? 0 : h*32;
#pragma unroll
            for (int p = 0; p < 4; p++) {
                const int rb = ((h*4 + s)*4 + p) * 3;
                float gx = bgx + tanh_fast(sbuf[(rb+0)*K1PX + v]) * 0.35f;
                float gy = bgy + tanh_fast(sbuf[(rb+1)*K1PX + v]) * 0.35f;
                float gz = bgz + tanh_fast(sbuf[(rb+2)*K1PX + v]) * 0.35f;
                float ix = fminf(fmaxf(((gx + 1.f)*fS - 1.f)*0.5f, 0.f), fS - 1.f);
                float iy = fminf(fmaxf(((gy + 1.f)*fS - 1.f)*0.5f, 0.f), fS - 1.f);
                float iz = fminf(fmaxf(((gz + 1.f)*fS - 1.f)*0.5f, 0.f), fS - 1.f);
                float x0f = floorf(ix), y0f = floorf(iy), z0f = floorf(iz);
                float wx = ix - x0f, wy = iy - y0f, wz = iz - z0f;
                int x0 = (int)x0f, y0 = (int)y0f, z0 = (int)z0f;
                int flags = ((x0 < S-1) ? 4 : 0) | ((y0 < S-1) ? 2 : 0) | ((z0 < S-1) ? 1 : 0);
                int base = ((z0*S + y0)*S + x0)*stride + hofs;
                float aw = e[s*4 + p] * inv;
                float wx1 = 1.f - wx, wy1 = 1.f - wy, wz1 = 1.f - wz;
                float p00 = wz1*wy1, p01 = wz1*wy, p10 = wz*wy1, p11 = wz*wy;
                unsigned u0 = (unsigned)(p00*wx1*65535.f + 0.5f);
                unsigned u1 = (unsigned)(p00*wx *65535.f + 0.5f);
                unsigned u2 = (unsigned)(p01*wx1*65535.f + 0.5f);
                unsigned u3 = (unsigned)(p01*wx *65535.f + 0.5f);
                unsigned u4 = (unsigned)(p10*wx1*65535.f + 0.5f);
                unsigned u5 = (unsigned)(p10*wx *65535.f + 0.5f);
                unsigned u6 = (unsigned)(p11*wx1*65535.f + 0.5f);
                unsigned u7 = (unsigned)(p11*wx *65535.f + 0.5f);
                uint4 B = make_uint4((u1<<16)|u0, (u3<<16)|u2, (u5<<16)|u4, (u7<<16)|u6);
                int2 A = make_int2(base | flags, __float_as_int(aw * (1.f/65535.f)));
                int idx = (h*16 + s*4 + p)*4096 + n;
                g_mdA[idx] = A;
                g_mdB[idx] = B;
            }
        }
        return;
    }

    // ================= k3 role: HMMA projections scales 1..3 =================
    const int b2 = b - 256;
    const float* vsrc; const __half* Wg; __half* outv;
    int C, Nv, nb;
    if (b2 < 512)      { vsrc = v1; Wg = g_Wvh;         outv = g_val1; C = 64;  Nv = 32768; nb = b2*64; }
    else if (b2 < 576) { vsrc = v2; Wg = g_Wvh + 16384; outv = g_val2; C = 128; Nv = 4096;  nb = (b2-512)*64; }
    else               { vsrc = v3; Wg = g_Wvh + 49152; outv = g_val3; C = 256; Nv = 512;   nb = (b2-576)*64; }

    __half* Xt = (__half*)sm1;     // [64][18]
    __half* Ds = (__half*)sm1;     // reuse: [64][264]

    const int warp = tid >> 5, lane = tid & 31;
    const int grp = lane >> 2, tg = lane & 3;
    const int wbase = warp * 32;

    float acc[2][8][4];
#pragma unroll
    for (int mt = 0; mt < 2; mt++)
#pragma unroll
        for (int nt = 0; nt < 8; nt++)
#pragma unroll
            for (int i = 0; i < 4; i++) acc[mt][nt][i] = 0.f;

    const int xk = tid >> 4, xv = (tid & 15) * 4;

    for (int kc = 0; kc < C; kc += 16) {
        float4 x4 = *(const float4*)&vsrc[(size_t)(kc + xk)*Nv + nb + xv];
        Xt[(xv+0)*18 + xk] = __float2half_rn(x4.x);
        Xt[(xv+1)*18 + xk] = __float2half_rn(x4.y);
        Xt[(xv+2)*18 + xk] = __float2half_rn(x4.z);
        Xt[(xv+3)*18 + xk] = __float2half_rn(x4.w);
        __syncthreads();

        unsigned af[2][4];
#pragma unroll
        for (int mt = 0; mt < 2; mt++) {
            const __half* Ar = Wg + (size_t)(wbase + mt*16 + grp)*C + kc;
            af[mt][0] = *(const unsigned*)(Ar + 2*tg);
            af[mt][1] = *(const unsigned*)(Ar + 8*C + 2*tg);
            af[mt][2] = *(const unsigned*)(Ar + 2*tg + 8);
            af[mt][3] = *(const unsigned*)(Ar + 8*C + 2*tg + 8);
        }
#pragma unroll
        for (int nt = 0; nt < 8; nt++) {
            const __half* Br = Xt + (nt*8 + grp)*18 + 2*tg;
            unsigned b0 = *(const unsigned*)Br;
            unsigned b1 = *(const unsigned*)(Br + 8);
#pragma unroll
            for (int mt = 0; mt < 2; mt++) {
                asm volatile(
                    "mma.sync.aligned.m16n8k16.row.col.f32.f16.f16.f32 "
                    "{%0,%1,%2,%3}, {%4,%5,%6,%7}, {%8,%9}, {%0,%1,%2,%3};"
                    : "+f"(acc[mt][nt][0]), "+f"(acc[mt][nt][1]),
                      "+f"(acc[mt][nt][2]), "+f"(acc[mt][nt][3])
                    : "r"(af[mt][0]), "r"(af[mt][1]), "r"(af[mt][2]), "r"(af[mt][3]),
                      "r"(b0), "r"(b1));
            }
        }
        __syncthreads();
    }

#pragma unroll
    for (int mt = 0; mt < 2; mt++) {
        const int slot = wbase + mt*16 + grp;
#pragma unroll
        for (int nt = 0; nt < 8; nt++) {
            const int vv = nt*8 + 2*tg;
            Ds[vv*264 + slot]         = __float2half_rn(acc[mt][nt][0]);
            Ds[(vv+1)*264 + slot]     = __float2half_rn(acc[mt][nt][1]);
            Ds[vv*264 + slot + 8]     = __float2half_rn(acc[mt][nt][2]);
            Ds[(vv+1)*264 + slot + 8] = __float2half_rn(acc[mt][nt][3]);
        }
    }
    __syncthreads();
    for (int i = tid; i < 2048; i += 256) {
        int v = i >> 5, j = i & 31;
        *reinterpret_cast<uint4*>(&outv[(size_t)(nb + v)*256 + j*8]) =
            *reinterpret_cast<const uint4*>(&Ds[v*264 + j*8]);
    }
}

// ---------------- K4: gather with compact md, occ-forced ----------------
__global__ void __launch_bounds__(512, 3) k4_sample() {
    const int tid = threadIdx.x;
    const int warp = tid >> 5, lane = tid & 31;
    const int gw = blockIdx.x*16 + warp;
    const int h = gw >> 12, n = gw & 4095;
    const int corner = lane >> 2, q8 = (lane & 3) * 8;
    const int cx = corner & 1, cy = (corner >> 1) & 1, cz = corner >> 2;

    float2 acc0[4], acc1[4];
#pragma unroll
    for (int j = 0; j < 4; j++) { acc0[j] = make_float2(0.f,0.f); acc1[j] = make_float2(0.f,0.f); }

    const int ptb = h*16*4096 + n;
    const unsigned short* mdw = reinterpret_cast<const unsigned short*>(g_mdB);

    // scale 0: stride 32, S=64
    {
        const int dxc = cx ? 32 : 0, dyc = cy ? 64*32 : 0, dzc = cz ? 64*64*32 : 0;
#pragma unroll
        for (int p = 0; p < 4; p++) {
            int idx = ptb + p*4096;
            int2 A = g_mdA[idx];
            unsigned pw = mdw[idx*8 + corner];
            int bf = A.x;
            int off = (bf & ~7) + q8 + ((bf & 4) ? dxc : 0) + ((bf & 2) ? dyc : 0) + ((bf & 1) ? dzc : 0);
            float w = (float)pw * __int_as_float(A.y);
            union { uint4 u; __half2 hh[4]; } d;
            d.u = *reinterpret_cast<const uint4*>(g_v0ph + off);
#pragma unroll
            for (int j = 0; j < 4; j++) {
                float2 f = __half22float2(d.hh[j]);
                acc0[j].x += w*f.x; acc0[j].y += w*f.y;
            }
        }
    }
    // scales 1..3: stride 256
#pragma unroll
    for (int s = 1; s < 4; s++) {
        const __half* vptr = (s == 1) ? g_val1 : (s == 2) ? g_val2 : g_val3;
        const int S = 64 >> s;
        const int dxc = cx ? 256 : 0, dyc = cy ? S*256 : 0, dzc = cz ? S*S*256 : 0;
#pragma unroll
        for (int p = 0; p < 4; p++) {
            int idx = ptb + (s*4 + p)*4096;
            int2 A = g_mdA[idx];
            unsigned pw = mdw[idx*8 + corner];
            int bf = A.x;
            int off = (bf & ~7) + q8 + ((bf & 4) ? dxc : 0) + ((bf & 2) ? dyc : 0) + ((bf & 1) ? dzc : 0);
            float w = (float)pw * __int_as_float(A.y);
            union { uint4 u; __half2 hh[4]; } d;
            d.u = *reinterpret_cast<const uint4*>(vptr + off);
#pragma unroll
            for (int j = 0; j < 4; j++) {
                float2 f = __half22float2(d.hh[j]);
                acc1[j].x += w*f.x; acc1[j].y += w*f.y;
            }
        }
    }
#pragma unroll
    for (int m = 4; m <= 16; m <<= 1) {
#pragma unroll
        for (int j = 0; j < 4; j++) {
            acc0[j].x += __shfl_xor_sync(FULL, acc0[j].x, m);
            acc0[j].y += __shfl_xor_sync(FULL, acc0[j].y, m);
            acc1[j].x += __shfl_xor_sync(FULL, acc1[j].x, m);
            acc1[j].y += __shfl_xor_sync(FULL, acc1[j].y, m);
        }
    }
    if (lane < 4) {
        const int base = n*256 + h*32 + q8;
        *(float4*)&g_accA[base]     = make_float4(acc0[0].x, acc0[0].y, acc0[1].x, acc0[1].y);
        *(float4*)&g_accA[base + 4] = make_float4(acc0[2].x, acc0[2].y, acc0[3].x, acc0[3].y);
        *(float4*)&g_accB[base]     = make_float4(acc1[0].x, acc1[0].y, acc1[1].x, acc1[1].y);
        *(float4*)&g_accB[base + 4] = make_float4(acc1[2].x, acc1[2].y, acc1[3].x, acc1[3].y);
    }
}

// ---------------- K5: combined output GEMM [128][512] @ [512][4096], N-tile 32, grid 128 ----------------
#define K5PX 36
#define K5PW 132
__global__ void __launch_bounds__(256) k5_out() {
    __shared__ __align__(16) float xs[32*K5PX];
    __shared__ __align__(16) float sW[32*K5PW];
    const int tid = threadIdx.x;
    const int nb = blockIdx.x * 32;
    const int rg = tid >> 4, cg = tid & 15;
    const int rbase = rg * 8;
    const int lv = tid >> 3, lk = (tid & 7) * 4;

    unsigned long long acc2[8];
#pragma unroll
    for (int i = 0; i < 8; i++) acc2[i] = 0ull;

    for (int kc = 0; kc < 512; kc += 32) {
        __syncthreads();
        {
            const float* srcbuf = (kc < 256) ? g_accA : g_accB;
            const int ko = kc & 255;
            float4 x4 = *(const float4*)&srcbuf[(nb + lv)*256 + ko + lk];
            xs[(lk+0)*K5PX + lv] = x4.x;
            xs[(lk+1)*K5PX + lv] = x4.y;
            xs[(lk+2)*K5PX + lv] = x4.z;
            xs[(lk+3)*K5PX + lv] = x4.w;
        }
        for (int e = tid; e < 32*32; e += 256) {
            int k = e >> 5, c4 = e & 31;
            *(float4*)&sW[k*K5PW + c4*4] = *(const float4*)&g_WcombT[(kc + k)*128 + c4*4];
        }
        __syncthreads();
#pragma unroll
        for (int k = 0; k < 32; k++) {
            const float* wr = &sW[k*K5PW + rbase];
            float4 wa = *(const float4*)(wr);
            float4 wb = *(const float4*)(wr + 4);
            float w[8] = {wa.x, wa.y, wa.z, wa.w, wb.x, wb.y, wb.z, wb.w};
            unsigned long long xv = *(const unsigned long long*)&xs[k*K5PX + cg*2];
#pragma unroll
            for (int i = 0; i < 8; i++) {
                unsigned long long wp = pack2(w[i], w[i]);
                fma2(acc2[i], wp, xv);
            }
        }
    }
#pragma unroll
    for (int i = 0; i < 8; i++) {
        float2 f = u2f(acc2[i]);
        *(float2*)&g_outbuf[(rbase + i)*4096 + nb + cg*2] = f;
    }
}

// ---------------- K6: InstanceNorm per channel ----------------
__global__ void __launch_bounds__(256) k6_norm(const float* __restrict__ gamma,
                                               const float* __restrict__ beta,
                                               float* __restrict__ out) {
    const int c = blockIdx.x, tid = threadIdx.x;
    const float* row = &g_outbuf[c*4096];
    float s = 0.f, s2 = 0.f;
    for (int i = tid; i < 4096; i += 256) { float x = row[i]; s += x; s2 += x*x; }
#pragma unroll
    for (int m = 16; m > 0; m >>= 1) {
        s  += __shfl_xor_sync(FULL, s,  m);
        s2 += __shfl_xor_sync(FULL, s2, m);
    }
    __shared__ float rs[8], rq[8];
    __shared__ float smu, srstd;
    if ((tid & 31) == 0) { rs[tid >> 5] = s; rq[tid >> 5] = s2; }
    __syncthreads();
    if (tid == 0) {
        float ts = 0.f, tq = 0.f;
        for (int i = 0; i < 8; i++) { ts += rs[i]; tq += rq[i]; }
        float mu = ts * (1.f/4096.f);
        smu = mu;
        srstd = rsqrtf(tq * (1.f/4096.f) - mu*mu + 1e-5f);
    }
    __syncthreads();
    const float g = gamma[c] * srstd, b = beta[c], mu = smu;
    for (int i = tid; i < 4096; i += 256)
        out[c*4096 + i] = (row[i] - mu) * g + b;
}

// ---------------- launch ----------------
extern "C" void kernel_launch(void* const* d_in, const int* in_sizes, int n_in,
                              void* d_out, int out_size) {
    const float* qf    = (const float*)d_in[0];
    const float* v0    = (const float*)d_in[1];
    const float* v1    = (const float*)d_in[2];
    const float* v2    = (const float*)d_in[3];
    const float* v3    = (const float*)d_in[4];
    const float* Wq    = (const float*)d_in[5];
    const float* Wv0   = (const float*)d_in[6];
    const float* Wv1   = (const float*)d_in[7];
    const float* Wv2   = (const float*)d_in[8];
    const float* Wv3   = (const float*)d_in[9];
    const float* Woff  = (const float*)d_in[10];
    const float* boff  = (const float*)d_in[11];
    const float* Wwt   = (const float*)d_in[12];
    const float* bwt   = (const float*)d_in[13];
    const float* Wout  = (const float*)d_in[14];
    const float* gamma = (const float*)d_in[15];
    const float* beta  = (const float*)d_in[16];
    float* out = (float*)d_out;

    // Order: ncu's captured launch (#4) is the occupancy-fixed k4_sample.
    k0_fold<<<704, 128>>>(Woff, Wwt, Wq, boff, bwt, Wout, Wv0, Wv1, Wv2, Wv3);
    k2_packv0<<<2048, 256>>>(v0);
    k13_fused<<<840, 256>>>(qf, v1, v2, v3);
    k4_sample<<<2048, 512>>>();
    k5_out<<<128, 256>>>();
    k6_norm<<<128, 256>>>(gamma, beta, out);
}